// round 1
// baseline (speedup 1.0000x reference)
#include <cuda_runtime.h>
#include <stdint.h>

#define N 4096
#define D 768
#define BM 128
#define BN 128
#define BK 32
#define CSPLIT 512   // columns handled per block (4 tiles of 128)
#define MARGIN 1.0f

__device__ float g_e[N * D];     // normalized embeddings
__device__ float g_dap[N];       // hardest-positive distance (max), >=0
__device__ float g_dan[N];       // hardest-negative distance (min), >=0

// ---------------------------------------------------------------------------
__global__ void init_kernel() {
    int i = blockIdx.x * blockDim.x + threadIdx.x;
    if (i < N) {
        g_dap[i] = 0.0f;
        g_dan[i] = __int_as_float(0x7f800000);  // +inf
    }
}

// ---------------------------------------------------------------------------
// One block per row, 256 threads, 3 elements per thread (D=768).
__global__ void normalize_kernel(const float* __restrict__ emb) {
    int row = blockIdx.x;
    const float* src = emb + (size_t)row * D;
    float* dst = g_e + (size_t)row * D;

    float v[3];
    float s = 0.0f;
#pragma unroll
    for (int t = 0; t < 3; t++) {
        v[t] = src[threadIdx.x + t * 256];
        s += v[t] * v[t];
    }
    // warp reduce
#pragma unroll
    for (int o = 16; o > 0; o >>= 1) s += __shfl_xor_sync(0xffffffffu, s, o);
    __shared__ float red[8];
    if ((threadIdx.x & 31) == 0) red[threadIdx.x >> 5] = s;
    __syncthreads();
    if (threadIdx.x < 32) {
        float x = (threadIdx.x < 8) ? red[threadIdx.x] : 0.0f;
#pragma unroll
        for (int o = 4; o > 0; o >>= 1) x += __shfl_xor_sync(0xffffffffu, x, o);
        if (threadIdx.x == 0) red[0] = x;
    }
    __syncthreads();
    float nrm = sqrtf(red[0]);
    float inv = 1.0f / fmaxf(nrm, 1e-12f);
#pragma unroll
    for (int t = 0; t < 3; t++) dst[threadIdx.x + t * 256] = v[t] * inv;
}

// ---------------------------------------------------------------------------
// Fused GEMM (e @ e^T tile) + batch-hard mining.
// Grid: (N/BM, N/CSPLIT). 256 threads; each thread owns an 8x8 microtile.
__global__ void __launch_bounds__(256)
mine_kernel(const long long* __restrict__ labels) {
    __shared__ float As[BK][BM + 4];
    __shared__ float Bs[BK][BN + 4];
    __shared__ int s_lr[BM];
    __shared__ int s_lc[BN];

    const int tid = threadIdx.x;
    const int tx = tid & 15;   // column group (8 cols each)
    const int ty = tid >> 4;   // row group (8 rows each)
    const int rowBase = blockIdx.x * BM;
    const int colBase0 = blockIdx.y * CSPLIT;

    if (tid < BM) s_lr[tid] = (int)labels[rowBase + tid];

    float pmax[8], nmin[8];
#pragma unroll
    for (int i = 0; i < 8; i++) {
        pmax[i] = 0.0f;
        nmin[i] = __int_as_float(0x7f800000);
    }

    for (int ct = 0; ct < CSPLIT / BN; ct++) {
        const int colBase = colBase0 + ct * BN;
        __syncthreads();  // previous iteration done with smem
        if (tid < BN) s_lc[tid] = (int)labels[colBase + tid];

        float acc[8][8];
#pragma unroll
        for (int i = 0; i < 8; i++)
#pragma unroll
            for (int j = 0; j < 8; j++) acc[i][j] = 0.0f;

        for (int k0 = 0; k0 < D; k0 += BK) {
            __syncthreads();
            // Load 128x32 tiles of A (anchor rows) and B (candidate rows).
#pragma unroll
            for (int t = 0; t < 4; t++) {
                int f4 = tid + t * 256;   // 0..1023
                int r = f4 >> 3;          // row within tile
                int kq = f4 & 7;          // which float4 along K
                float4 a = *reinterpret_cast<const float4*>(
                    &g_e[(size_t)(rowBase + r) * D + k0 + kq * 4]);
                As[kq * 4 + 0][r] = a.x;
                As[kq * 4 + 1][r] = a.y;
                As[kq * 4 + 2][r] = a.z;
                As[kq * 4 + 3][r] = a.w;
                float4 b = *reinterpret_cast<const float4*>(
                    &g_e[(size_t)(colBase + r) * D + k0 + kq * 4]);
                Bs[kq * 4 + 0][r] = b.x;
                Bs[kq * 4 + 1][r] = b.y;
                Bs[kq * 4 + 2][r] = b.z;
                Bs[kq * 4 + 3][r] = b.w;
            }
            __syncthreads();
#pragma unroll
            for (int k = 0; k < BK; k++) {
                float af[8], bf[8];
                float4 a0 = *reinterpret_cast<const float4*>(&As[k][ty * 8]);
                float4 a1 = *reinterpret_cast<const float4*>(&As[k][ty * 8 + 4]);
                float4 b0 = *reinterpret_cast<const float4*>(&Bs[k][tx * 8]);
                float4 b1 = *reinterpret_cast<const float4*>(&Bs[k][tx * 8 + 4]);
                af[0] = a0.x; af[1] = a0.y; af[2] = a0.z; af[3] = a0.w;
                af[4] = a1.x; af[5] = a1.y; af[6] = a1.z; af[7] = a1.w;
                bf[0] = b0.x; bf[1] = b0.y; bf[2] = b0.z; bf[3] = b0.w;
                bf[4] = b1.x; bf[5] = b1.y; bf[6] = b1.z; bf[7] = b1.w;
#pragma unroll
                for (int i = 0; i < 8; i++)
#pragma unroll
                    for (int j = 0; j < 8; j++)
                        acc[i][j] += af[i] * bf[j];
            }
        }

        // Mining on this 128x128 tile.
#pragma unroll
        for (int i = 0; i < 8; i++) {
            const int r = rowBase + ty * 8 + i;
            const int lr = s_lr[ty * 8 + i];
#pragma unroll
            for (int j = 0; j < 8; j++) {
                const int c = colBase + tx * 8 + j;
                float d = sqrtf(fmaxf(2.0f - 2.0f * acc[i][j], 0.0f) + 1e-12f);
                const int lc = s_lc[tx * 8 + j];
                if (lr == lc) {
                    if (r != c) pmax[i] = fmaxf(pmax[i], d);
                } else {
                    nmin[i] = fminf(nmin[i], d);
                }
            }
        }
    }

    // Reduce across the 16 column-lanes sharing each anchor row (same ty ->
    // consecutive lanes within a half-warp), then one atomic per row.
#pragma unroll
    for (int i = 0; i < 8; i++) {
        float p = pmax[i], n = nmin[i];
#pragma unroll
        for (int o = 8; o > 0; o >>= 1) {
            p = fmaxf(p, __shfl_xor_sync(0xffffffffu, p, o, 16));
            n = fminf(n, __shfl_xor_sync(0xffffffffu, n, o, 16));
        }
        if (tx == 0) {
            int r = rowBase + ty * 8 + i;
            // distances are >= 0, so int ordering == float ordering
            atomicMax(reinterpret_cast<int*>(&g_dap[r]), __float_as_int(p));
            atomicMin(reinterpret_cast<int*>(&g_dan[r]), __float_as_int(n));
        }
    }
}

// ---------------------------------------------------------------------------
__global__ void finalize_kernel(float* __restrict__ out) {
    const int tid = threadIdx.x;  // 256 threads
    float sum = 0.0f, cnt = 0.0f;
    for (int i = tid; i < N; i += 256) {
        float dap = g_dap[i];
        if (dap > 0.0f) {  // at least one positive existed
            cnt += 1.0f;
            float l = dap - g_dan[i] + MARGIN;
            sum += fmaxf(l, 0.0f);
        }
    }
#pragma unroll
    for (int o = 16; o > 0; o >>= 1) {
        sum += __shfl_xor_sync(0xffffffffu, sum, o);
        cnt += __shfl_xor_sync(0xffffffffu, cnt, o);
    }
    __shared__ float rs[8], rc[8];
    if ((tid & 31) == 0) { rs[tid >> 5] = sum; rc[tid >> 5] = cnt; }
    __syncthreads();
    if (tid == 0) {
        float S = 0.0f, C = 0.0f;
#pragma unroll
        for (int w = 0; w < 8; w++) { S += rs[w]; C += rc[w]; }
        out[0] = S / fmaxf(C, 1.0f);
    }
}

// ---------------------------------------------------------------------------
extern "C" void kernel_launch(void* const* d_in, const int* in_sizes, int n_in,
                              void* d_out, int out_size) {
    const float* emb = (const float*)d_in[0];
    const long long* labels = (const long long*)d_in[1];
    float* out = (float*)d_out;

    init_kernel<<<(N + 255) / 256, 256>>>();
    normalize_kernel<<<N, 256>>>(emb);
    dim3 grid(N / BM, N / CSPLIT);
    mine_kernel<<<grid, 256>>>(labels);
    finalize_kernel<<<1, 256>>>(out);
}

// round 3
// speedup vs baseline: 1.7638x; 1.7638x over previous
#include <cuda_runtime.h>
#include <stdint.h>

#define N 4096
#define D 768
#define BM 128
#define BN 128
#define BK 32
#define CSPLIT 512
#define MARGIN 1.0f
#define ASTRIDE 36            // floats per smem row (pad 4)
#define BUF_FLOATS (128 * ASTRIDE)

__device__ __align__(128) float g_e[N * D];  // normalized, tf32-rounded
__device__ float g_pkey[N];  // min positive dot + 4 (inf if none)
__device__ float g_nkey[N];  // max negative dot + 4 (0 if none)

// ---------------- PTX helpers ---------------------------------------------
__device__ __forceinline__ uint32_t smem_u32(const void* p) {
    uint32_t a;
    asm("{ .reg .u64 t; cvta.to.shared.u64 t, %1; cvt.u32.u64 %0, t; }"
        : "=r"(a) : "l"(p));
    return a;
}
#define CP_ASYNC16(dst, src) \
    asm volatile("cp.async.cg.shared.global [%0], [%1], 16;" \
                 :: "r"(dst), "l"(src) : "memory")
#define CP_COMMIT() asm volatile("cp.async.commit_group;" ::: "memory")
#define CP_WAIT(n)  asm volatile("cp.async.wait_group %0;" :: "n"(n) : "memory")

__device__ __forceinline__ void mma_tf32(float* d, const uint32_t* a,
                                         const uint32_t* b) {
    asm volatile(
        "mma.sync.aligned.m16n8k8.row.col.f32.tf32.tf32.f32 "
        "{%0,%1,%2,%3}, {%4,%5,%6,%7}, {%8,%9}, {%0,%1,%2,%3};"
        : "+f"(d[0]), "+f"(d[1]), "+f"(d[2]), "+f"(d[3])
        : "r"(a[0]), "r"(a[1]), "r"(a[2]), "r"(a[3]), "r"(b[0]), "r"(b[1]));
}

// ---------------------------------------------------------------------------
__global__ void init_kernel() {
    int i = blockIdx.x * blockDim.x + threadIdx.x;
    if (i < N) {
        g_pkey[i] = __int_as_float(0x7f800000);  // +inf
        g_nkey[i] = 0.0f;                        // sentinel
    }
}

// ---------------------------------------------------------------------------
__global__ void normalize_kernel(const float* __restrict__ emb) {
    int row = blockIdx.x;
    const float* src = emb + (size_t)row * D;
    float* dst = g_e + (size_t)row * D;

    float v[3];
    float s = 0.0f;
#pragma unroll
    for (int t = 0; t < 3; t++) {
        v[t] = src[threadIdx.x + t * 256];
        s += v[t] * v[t];
    }
#pragma unroll
    for (int o = 16; o > 0; o >>= 1) s += __shfl_xor_sync(0xffffffffu, s, o);
    __shared__ float red[8];
    if ((threadIdx.x & 31) == 0) red[threadIdx.x >> 5] = s;
    __syncthreads();
    if (threadIdx.x < 32) {
        float x = (threadIdx.x < 8) ? red[threadIdx.x] : 0.0f;
#pragma unroll
        for (int o = 4; o > 0; o >>= 1) x += __shfl_xor_sync(0xffffffffu, x, o);
        if (threadIdx.x == 0) red[0] = x;
    }
    __syncthreads();
    float inv = 1.0f / fmaxf(sqrtf(red[0]), 1e-12f);
#pragma unroll
    for (int t = 0; t < 3; t++) {
        float x = v[t] * inv;
        uint32_t r;
        asm("cvt.rna.tf32.f32 %0, %1;" : "=r"(r) : "f"(x));
        dst[threadIdx.x + t * 256] = __uint_as_float(r);
    }
}

// ---------------------------------------------------------------------------
// Fused tf32 mma.sync GEMM + batch-hard mining (dot domain).
// 256 threads = 8 warps in 2x4 grid; warp tile 64x32 (4x4 m16n8k8 MMAs).
__global__ void __launch_bounds__(256, 1)
mine_mma(const long long* __restrict__ labels) {
    extern __shared__ float smem[];
    // layout: A[0], A[1], B[0], B[1] each BUF_FLOATS
    float* Abuf[2] = {smem, smem + BUF_FLOATS};
    float* Bbuf[2] = {smem + 2 * BUF_FLOATS, smem + 3 * BUF_FLOATS};
    const uint32_t sb = smem_u32(smem);

    const int tid = threadIdx.x;
    const int lane = tid & 31;
    const int warp = tid >> 5;
    const int wy = warp >> 2;         // 0..1  (row block of 64)
    const int wx = warp & 3;          // 0..3  (col block of 32)
    const int g = lane >> 2;          // 0..7
    const int t = lane & 3;           // 0..3

    const int rowBase = blockIdx.x * BM;
    const int colBase0 = blockIdx.y * CSPLIT;

    // row labels for this thread's 8 rows (fixed across col tiles)
    int lr[4][2];
#pragma unroll
    for (int mt = 0; mt < 4; mt++) {
        int r0 = rowBase + wy * 64 + mt * 16 + g;
        lr[mt][0] = (int)labels[r0];
        lr[mt][1] = (int)labels[r0 + 8];
    }

    for (int ct = 0; ct < CSPLIT / BN; ct++) {
        const int colBase = colBase0 + ct * BN;

        float acc[4][4][4];
#pragma unroll
        for (int mt = 0; mt < 4; mt++)
#pragma unroll
            for (int nt = 0; nt < 4; nt++)
#pragma unroll
                for (int q = 0; q < 4; q++) acc[mt][nt][q] = 0.0f;

        // ---- prefetch stage 0 ----
        {
            const float* srcA = g_e + (size_t)rowBase * D;
            const float* srcB = g_e + (size_t)colBase * D;
#pragma unroll
            for (int i = 0; i < 4; i++) {
                int idx = tid + i * 256;          // 0..1023 float4 slots
                int row = idx >> 3, q = idx & 7;
                CP_ASYNC16(sb + (0 * BUF_FLOATS + row * ASTRIDE + q * 4) * 4,
                           srcA + (size_t)row * D + q * 4);
                CP_ASYNC16(sb + (2 * BUF_FLOATS + row * ASTRIDE + q * 4) * 4,
                           srcB + (size_t)row * D + q * 4);
            }
            CP_COMMIT();
        }

        for (int st = 0; st < D / BK; st++) {
            const int cur = st & 1;
            if (st + 1 < D / BK) {
                const int nxt = (st + 1) & 1;
                const int k0 = (st + 1) * BK;
                const float* srcA = g_e + (size_t)rowBase * D + k0;
                const float* srcB = g_e + (size_t)colBase * D + k0;
#pragma unroll
                for (int i = 0; i < 4; i++) {
                    int idx = tid + i * 256;
                    int row = idx >> 3, q = idx & 7;
                    CP_ASYNC16(
                        sb + (nxt * BUF_FLOATS + row * ASTRIDE + q * 4) * 4,
                        srcA + (size_t)row * D + q * 4);
                    CP_ASYNC16(
                        sb + ((2 + nxt) * BUF_FLOATS + row * ASTRIDE + q * 4) * 4,
                        srcB + (size_t)row * D + q * 4);
                }
                CP_COMMIT();
                CP_WAIT(1);
            } else {
                CP_WAIT(0);
            }
            __syncthreads();

            const float* As = Abuf[cur];
            const float* Bs = Bbuf[cur];
#pragma unroll
            for (int ks = 0; ks < 4; ks++) {
                uint32_t a[4][4], b[4][2];
#pragma unroll
                for (int mt = 0; mt < 4; mt++) {
                    int r = wy * 64 + mt * 16 + g;
                    int kc = ks * 8 + t;
                    a[mt][0] = __float_as_uint(As[r * ASTRIDE + kc]);
                    a[mt][1] = __float_as_uint(As[(r + 8) * ASTRIDE + kc]);
                    a[mt][2] = __float_as_uint(As[r * ASTRIDE + kc + 4]);
                    a[mt][3] = __float_as_uint(As[(r + 8) * ASTRIDE + kc + 4]);
                }
#pragma unroll
                for (int nt = 0; nt < 4; nt++) {
                    int c = wx * 32 + nt * 8 + g;
                    int kc = ks * 8 + t;
                    b[nt][0] = __float_as_uint(Bs[c * ASTRIDE + kc]);
                    b[nt][1] = __float_as_uint(Bs[c * ASTRIDE + kc + 4]);
                }
#pragma unroll
                for (int mt = 0; mt < 4; mt++)
#pragma unroll
                    for (int nt = 0; nt < 4; nt++)
                        mma_tf32(acc[mt][nt], a[mt], b[nt]);
            }
            __syncthreads();
        }

        // ---- mining on this 128x128 tile (dot domain) ----
        float pmin[4][2], nmax[4][2];
#pragma unroll
        for (int mt = 0; mt < 4; mt++) {
            pmin[mt][0] = pmin[mt][1] = __int_as_float(0x7f800000);
            nmax[mt][0] = nmax[mt][1] = -__int_as_float(0x7f800000);
        }
#pragma unroll
        for (int nt = 0; nt < 4; nt++) {
            int c0 = colBase + wx * 32 + nt * 8 + t * 2;
            int lc0 = (int)labels[c0];
            int lc1 = (int)labels[c0 + 1];
#pragma unroll
            for (int mt = 0; mt < 4; mt++) {
                int r0 = rowBase + wy * 64 + mt * 16 + g;
                int r1 = r0 + 8;
                float d0 = acc[mt][nt][0], d1 = acc[mt][nt][1];
                float d2 = acc[mt][nt][2], d3 = acc[mt][nt][3];
                // row r0
                if (lc0 == lr[mt][0]) {
                    if (c0 != r0) pmin[mt][0] = fminf(pmin[mt][0], d0);
                } else nmax[mt][0] = fmaxf(nmax[mt][0], d0);
                if (lc1 == lr[mt][0]) {
                    if (c0 + 1 != r0) pmin[mt][0] = fminf(pmin[mt][0], d1);
                } else nmax[mt][0] = fmaxf(nmax[mt][0], d1);
                // row r1
                if (lc0 == lr[mt][1]) {
                    if (c0 != r1) pmin[mt][1] = fminf(pmin[mt][1], d2);
                } else nmax[mt][1] = fmaxf(nmax[mt][1], d2);
                if (lc1 == lr[mt][1]) {
                    if (c0 + 1 != r1) pmin[mt][1] = fminf(pmin[mt][1], d3);
                } else nmax[mt][1] = fmaxf(nmax[mt][1], d3);
            }
        }
        // reduce across the 4 lanes of each quad (same rows, different cols)
#pragma unroll
        for (int mt = 0; mt < 4; mt++)
#pragma unroll
            for (int h = 0; h < 2; h++) {
                float p = pmin[mt][h], n = nmax[mt][h];
                p = fminf(p, __shfl_xor_sync(0xffffffffu, p, 1));
                p = fminf(p, __shfl_xor_sync(0xffffffffu, p, 2));
                n = fmaxf(n, __shfl_xor_sync(0xffffffffu, n, 1));
                n = fmaxf(n, __shfl_xor_sync(0xffffffffu, n, 2));
                if (t == 0) {
                    int r = rowBase + wy * 64 + mt * 16 + g + h * 8;
                    if (p < 1e30f)
                        atomicMin(reinterpret_cast<int*>(&g_pkey[r]),
                                  __float_as_int(p + 4.0f));
                    if (n > -1e30f)
                        atomicMax(reinterpret_cast<int*>(&g_nkey[r]),
                                  __float_as_int(n + 4.0f));
                }
            }
        __syncthreads();  // smem reuse safety for next ct
    }
}

// ---------------------------------------------------------------------------
__global__ void finalize_kernel(float* __restrict__ out) {
    const int tid = threadIdx.x;
    float sum = 0.0f, cnt = 0.0f;
    for (int i = tid; i < N; i += 256) {
        float pk = g_pkey[i];
        float nk = g_nkey[i];
        if (pk < 1e30f) {
            cnt += 1.0f;
            float dap = sqrtf(fmaxf(2.0f - 2.0f * (pk - 4.0f), 0.0f) + 1e-12f);
            float dan = (nk > 0.0f)
                ? sqrtf(fmaxf(2.0f - 2.0f * (nk - 4.0f), 0.0f) + 1e-12f)
                : 1e30f;
            sum += fmaxf(dap - dan + MARGIN, 0.0f);
        }
    }
#pragma unroll
    for (int o = 16; o > 0; o >>= 1) {
        sum += __shfl_xor_sync(0xffffffffu, sum, o);
        cnt += __shfl_xor_sync(0xffffffffu, cnt, o);
    }
    __shared__ float rs[8], rc[8];
    if ((tid & 31) == 0) { rs[tid >> 5] = sum; rc[tid >> 5] = cnt; }
    __syncthreads();
    if (tid == 0) {
        float S = 0.0f, C = 0.0f;
#pragma unroll
        for (int w = 0; w < 8; w++) { S += rs[w]; C += rc[w]; }
        out[0] = S / fmaxf(C, 1.0f);
    }
}

// ---------------------------------------------------------------------------
extern "C" void kernel_launch(void* const* d_in, const int* in_sizes, int n_in,
                              void* d_out, int out_size) {
    const float* emb = (const float*)d_in[0];
    const long long* labels = (const long long*)d_in[1];
    float* out = (float*)d_out;

    static int configured = 0;
    if (!configured) {
        cudaFuncSetAttribute(mine_mma, cudaFuncAttributeMaxDynamicSharedMemorySize,
                             4 * BUF_FLOATS * 4);
        configured = 1;
    }

    init_kernel<<<(N + 255) / 256, 256>>>();
    normalize_kernel<<<N, 256>>>(emb);
    dim3 grid(N / BM, N / CSPLIT);
    mine_mma<<<grid, 256, 4 * BUF_FLOATS * 4>>>(labels);
    finalize_kernel<<<1, 256>>>(out);
}

// round 4
// speedup vs baseline: 10.3539x; 5.8703x over previous
#include <cuda_runtime.h>
#include <cuda_fp16.h>
#include <stdint.h>

#define N 4096
#define D 768
#define BM 128
#define BN 128
#define BKH 64            // halfs per pipeline stage (128 B per row)
#define NSTG (D / BKH)    // 12
#define MARGIN 1.0f
#define SH 72             // halfs per smem row (36 words) - conflict-free pad
#define BUF_HALFS (128 * SH)          // 9216 halfs = 18432 B
#define SMEM_BYTES (4 * BUF_HALFS * 2)  // 73728

#define NTILE 32          // 4096/128
#define NUNITS (NTILE * (NTILE + 1) / 2)  // 528

__device__ __align__(128) __half g_e[N * D];  // normalized fp16 embeddings
__device__ float g_pkey[N];  // min positive dot + 4 (inf if none)
__device__ float g_nkey[N];  // max negative dot + 4 (0 if none)

// ---------------- PTX helpers ---------------------------------------------
__device__ __forceinline__ uint32_t smem_u32(const void* p) {
    uint32_t a;
    asm("{ .reg .u64 t; cvta.to.shared.u64 t, %1; cvt.u32.u64 %0, t; }"
        : "=r"(a) : "l"(p));
    return a;
}
#define CP_ASYNC16(dst, src) \
    asm volatile("cp.async.cg.shared.global [%0], [%1], 16;" \
                 :: "r"(dst), "l"(src) : "memory")
#define CP_COMMIT() asm volatile("cp.async.commit_group;" ::: "memory")
#define CP_WAIT(n)  asm volatile("cp.async.wait_group %0;" :: "n"(n) : "memory")

__device__ __forceinline__ void mma_f16(float* d, const uint32_t* a,
                                        const uint32_t* b) {
    asm volatile(
        "mma.sync.aligned.m16n8k16.row.col.f32.f16.f16.f32 "
        "{%0,%1,%2,%3}, {%4,%5,%6,%7}, {%8,%9}, {%0,%1,%2,%3};"
        : "+f"(d[0]), "+f"(d[1]), "+f"(d[2]), "+f"(d[3])
        : "r"(a[0]), "r"(a[1]), "r"(a[2]), "r"(a[3]), "r"(b[0]), "r"(b[1]));
}

// ---------------------------------------------------------------------------
__global__ void init_kernel() {
    int i = blockIdx.x * blockDim.x + threadIdx.x;
    if (i < N) {
        g_pkey[i] = __int_as_float(0x7f800000);  // +inf
        g_nkey[i] = 0.0f;                        // sentinel
    }
}

// ---------------------------------------------------------------------------
__global__ void normalize_kernel(const float* __restrict__ emb) {
    int row = blockIdx.x;
    const float* src = emb + (size_t)row * D;
    __half* dst = g_e + (size_t)row * D;

    float v[3];
    float s = 0.0f;
#pragma unroll
    for (int t = 0; t < 3; t++) {
        v[t] = src[threadIdx.x + t * 256];
        s += v[t] * v[t];
    }
#pragma unroll
    for (int o = 16; o > 0; o >>= 1) s += __shfl_xor_sync(0xffffffffu, s, o);
    __shared__ float red[8];
    if ((threadIdx.x & 31) == 0) red[threadIdx.x >> 5] = s;
    __syncthreads();
    if (threadIdx.x < 32) {
        float x = (threadIdx.x < 8) ? red[threadIdx.x] : 0.0f;
#pragma unroll
        for (int o = 4; o > 0; o >>= 1) x += __shfl_xor_sync(0xffffffffu, x, o);
        if (threadIdx.x == 0) red[0] = x;
    }
    __syncthreads();
    float inv = 1.0f / fmaxf(sqrtf(red[0]), 1e-12f);
#pragma unroll
    for (int t = 0; t < 3; t++)
        dst[threadIdx.x + t * 256] = __float2half_rn(v[t] * inv);
}

// ---------------------------------------------------------------------------
// One upper-triangle 128x128 Gram tile per CTA; fp16 m16n8k16 MMA; batch-hard
// mining in dot domain, updating BOTH row-anchors and col-anchors.
__global__ void __launch_bounds__(256, 1)
mine_mma(const long long* __restrict__ labels) {
    extern __shared__ __half smem[];
    const uint32_t sb = smem_u32(smem);
    __shared__ int s_lr[128], s_lc[128];

    // triangle mapping: u -> (I, J) with I <= J, J-major within row I
    int u = blockIdx.x;
    int I = 0;
    while (u >= NTILE - I) { u -= NTILE - I; I++; }
    const int J = I + u;
    const int rowBase = I * BM;
    const int colBase = J * BN;

    const int tid = threadIdx.x;
    const int lane = tid & 31;
    const int warp = tid >> 5;
    const int wy = warp >> 2;   // 0..1
    const int wx = warp & 3;    // 0..3
    const int g = lane >> 2;    // 0..7
    const int t = lane & 3;     // 0..3

    if (tid < 128) s_lr[tid] = (int)labels[rowBase + tid];
    else s_lc[tid - 128] = (int)labels[colBase + tid - 128];

    float acc[4][4][4];
#pragma unroll
    for (int mt = 0; mt < 4; mt++)
#pragma unroll
        for (int nt = 0; nt < 4; nt++)
#pragma unroll
            for (int q = 0; q < 4; q++) acc[mt][nt][q] = 0.0f;

    // ---- prefetch stage 0 ----
    {
        const __half* srcA = g_e + (size_t)rowBase * D;
        const __half* srcB = g_e + (size_t)colBase * D;
#pragma unroll
        for (int i = 0; i < 4; i++) {
            int idx = tid + i * 256;      // 1024 16B-chunks per tile
            int row = idx >> 3, q = idx & 7;
            CP_ASYNC16(sb + row * 144 + q * 16,
                       srcA + (size_t)row * D + q * 8);
            CP_ASYNC16(sb + 2 * BUF_HALFS * 2 + row * 144 + q * 16,
                       srcB + (size_t)row * D + q * 8);
        }
        CP_COMMIT();
    }

    for (int st = 0; st < NSTG; st++) {
        const int cur = st & 1;
        if (st + 1 < NSTG) {
            const int nxt = (st + 1) & 1;
            const int k0 = (st + 1) * BKH;
            const __half* srcA = g_e + (size_t)rowBase * D + k0;
            const __half* srcB = g_e + (size_t)colBase * D + k0;
#pragma unroll
            for (int i = 0; i < 4; i++) {
                int idx = tid + i * 256;
                int row = idx >> 3, q = idx & 7;
                CP_ASYNC16(sb + nxt * BUF_HALFS * 2 + row * 144 + q * 16,
                           srcA + (size_t)row * D + q * 8);
                CP_ASYNC16(sb + (2 + nxt) * BUF_HALFS * 2 + row * 144 + q * 16,
                           srcB + (size_t)row * D + q * 8);
            }
            CP_COMMIT();
            CP_WAIT(1);
        } else {
            CP_WAIT(0);
        }
        __syncthreads();

        const uint32_t* As = (const uint32_t*)(smem + cur * BUF_HALFS);
        const uint32_t* Bs = (const uint32_t*)(smem + (2 + cur) * BUF_HALFS);
#pragma unroll
        for (int ks = 0; ks < 4; ks++) {       // 4 x k16 per stage
            const int kw = ks * 8;             // word offset of k-chunk
            uint32_t a[4][4], b[4][2];
#pragma unroll
            for (int mt = 0; mt < 4; mt++) {
                int r = wy * 64 + mt * 16 + g;
                a[mt][0] = As[r * 36 + kw + t];
                a[mt][1] = As[(r + 8) * 36 + kw + t];
                a[mt][2] = As[r * 36 + kw + 4 + t];
                a[mt][3] = As[(r + 8) * 36 + kw + 4 + t];
            }
#pragma unroll
            for (int nt = 0; nt < 4; nt++) {
                int c = wx * 32 + nt * 8 + g;
                b[nt][0] = Bs[c * 36 + kw + t];
                b[nt][1] = Bs[c * 36 + kw + 4 + t];
            }
#pragma unroll
            for (int mt = 0; mt < 4; mt++)
#pragma unroll
                for (int nt = 0; nt < 4; nt++)
                    mma_f16(acc[mt][nt], a[mt], b[nt]);
        }
        __syncthreads();
    }

    // ---- mining: both directions (rows = anchors, cols = anchors) ----------
    const float INF = __int_as_float(0x7f800000);
    float rp[4][2], rn[4][2];     // row-anchor trackers
    float cpm[4][2], cnm[4][2];   // col-anchor trackers (2 cols per thread)
#pragma unroll
    for (int i = 0; i < 4; i++)
#pragma unroll
        for (int h = 0; h < 2; h++) {
            rp[i][h] = INF; rn[i][h] = -INF;
            cpm[i][h] = INF; cnm[i][h] = -INF;
        }

#pragma unroll
    for (int nt = 0; nt < 4; nt++) {
        const int c0 = colBase + wx * 32 + nt * 8 + 2 * t;
        const int lc0 = s_lc[wx * 32 + nt * 8 + 2 * t];
        const int lc1 = s_lc[wx * 32 + nt * 8 + 2 * t + 1];
#pragma unroll
        for (int mt = 0; mt < 4; mt++) {
            const int r0 = rowBase + wy * 64 + mt * 16 + g;
            const int r1 = r0 + 8;
            const int lr0 = s_lr[wy * 64 + mt * 16 + g];
            const int lr1 = s_lr[wy * 64 + mt * 16 + g + 8];
            const float d0 = acc[mt][nt][0], d1 = acc[mt][nt][1];
            const float d2 = acc[mt][nt][2], d3 = acc[mt][nt][3];
            // (r0,c0)
            if (lr0 == lc0) {
                if (r0 != c0) { rp[mt][0] = fminf(rp[mt][0], d0);
                                cpm[nt][0] = fminf(cpm[nt][0], d0); }
            } else { rn[mt][0] = fmaxf(rn[mt][0], d0);
                     cnm[nt][0] = fmaxf(cnm[nt][0], d0); }
            // (r0,c1)
            if (lr0 == lc1) {
                if (r0 != c0 + 1) { rp[mt][0] = fminf(rp[mt][0], d1);
                                    cpm[nt][1] = fminf(cpm[nt][1], d1); }
            } else { rn[mt][0] = fmaxf(rn[mt][0], d1);
                     cnm[nt][1] = fmaxf(cnm[nt][1], d1); }
            // (r1,c0)
            if (lr1 == lc0) {
                if (r1 != c0) { rp[mt][1] = fminf(rp[mt][1], d2);
                                cpm[nt][0] = fminf(cpm[nt][0], d2); }
            } else { rn[mt][1] = fmaxf(rn[mt][1], d2);
                     cnm[nt][0] = fmaxf(cnm[nt][0], d2); }
            // (r1,c1)
            if (lr1 == lc1) {
                if (r1 != c0 + 1) { rp[mt][1] = fminf(rp[mt][1], d3);
                                    cpm[nt][1] = fminf(cpm[nt][1], d3); }
            } else { rn[mt][1] = fmaxf(rn[mt][1], d3);
                     cnm[nt][1] = fmaxf(cnm[nt][1], d3); }
        }
    }

    // row-anchor reduce across t (cols) -> lanes with t==0 do atomics
#pragma unroll
    for (int mt = 0; mt < 4; mt++)
#pragma unroll
        for (int h = 0; h < 2; h++) {
            float p = rp[mt][h], n = rn[mt][h];
            p = fminf(p, __shfl_xor_sync(0xffffffffu, p, 1));
            p = fminf(p, __shfl_xor_sync(0xffffffffu, p, 2));
            n = fmaxf(n, __shfl_xor_sync(0xffffffffu, n, 1));
            n = fmaxf(n, __shfl_xor_sync(0xffffffffu, n, 2));
            if (t == 0) {
                int r = rowBase + wy * 64 + mt * 16 + g + h * 8;
                if (p < 1e30f)
                    atomicMin(reinterpret_cast<int*>(&g_pkey[r]),
                              __float_as_int(p + 4.0f));
                if (n > -1e30f)
                    atomicMax(reinterpret_cast<int*>(&g_nkey[r]),
                              __float_as_int(n + 4.0f));
            }
        }

    // col-anchor reduce across g (rows) -> lanes with g==0 (lane 0..3)
#pragma unroll
    for (int nt = 0; nt < 4; nt++)
#pragma unroll
        for (int h = 0; h < 2; h++) {
            float p = cpm[nt][h], n = cnm[nt][h];
            p = fminf(p, __shfl_xor_sync(0xffffffffu, p, 4));
            p = fminf(p, __shfl_xor_sync(0xffffffffu, p, 8));
            p = fminf(p, __shfl_xor_sync(0xffffffffu, p, 16));
            n = fmaxf(n, __shfl_xor_sync(0xffffffffu, n, 4));
            n = fmaxf(n, __shfl_xor_sync(0xffffffffu, n, 8));
            n = fmaxf(n, __shfl_xor_sync(0xffffffffu, n, 16));
            if (g == 0) {
                int c = colBase + wx * 32 + nt * 8 + 2 * t + h;
                if (p < 1e30f)
                    atomicMin(reinterpret_cast<int*>(&g_pkey[c]),
                              __float_as_int(p + 4.0f));
                if (n > -1e30f)
                    atomicMax(reinterpret_cast<int*>(&g_nkey[c]),
                              __float_as_int(n + 4.0f));
            }
        }
}

// ---------------------------------------------------------------------------
__global__ void finalize_kernel(float* __restrict__ out) {
    const int tid = threadIdx.x;  // 1024 threads
    float sum = 0.0f, cnt = 0.0f;
    for (int i = tid; i < N; i += 1024) {
        float pk = g_pkey[i];
        float nk = g_nkey[i];
        if (pk < 1e30f) {
            cnt += 1.0f;
            float dap = sqrtf(fmaxf(2.0f - 2.0f * (pk - 4.0f), 0.0f) + 1e-12f);
            float dan = (nk > 0.0f)
                ? sqrtf(fmaxf(2.0f - 2.0f * (nk - 4.0f), 0.0f) + 1e-12f)
                : 1e30f;
            sum += fmaxf(dap - dan + MARGIN, 0.0f);
        }
    }
#pragma unroll
    for (int o = 16; o > 0; o >>= 1) {
        sum += __shfl_xor_sync(0xffffffffu, sum, o);
        cnt += __shfl_xor_sync(0xffffffffu, cnt, o);
    }
    __shared__ float rs[32], rc[32];
    if ((tid & 31) == 0) { rs[tid >> 5] = sum; rc[tid >> 5] = cnt; }
    __syncthreads();
    if (tid == 0) {
        float S = 0.0f, C = 0.0f;
#pragma unroll
        for (int w = 0; w < 32; w++) { S += rs[w]; C += rc[w]; }
        out[0] = S / fmaxf(C, 1.0f);
    }
}

// ---------------------------------------------------------------------------
extern "C" void kernel_launch(void* const* d_in, const int* in_sizes, int n_in,
                              void* d_out, int out_size) {
    const float* emb = (const float*)d_in[0];
    const long long* labels = (const long long*)d_in[1];
    float* out = (float*)d_out;

    static int configured = 0;
    if (!configured) {
        cudaFuncSetAttribute(mine_mma, cudaFuncAttributeMaxDynamicSharedMemorySize,
                             SMEM_BYTES);
        configured = 1;
    }

    init_kernel<<<(N + 255) / 256, 256>>>();
    normalize_kernel<<<N, 256>>>(emb);
    mine_mma<<<NUNITS, 256, SMEM_BYTES>>>(labels);
    finalize_kernel<<<1, 1024>>>(out);
}

// round 5
// speedup vs baseline: 11.9549x; 1.1546x over previous
#include <cuda_runtime.h>
#include <cuda_fp16.h>
#include <stdint.h>

#define N 4096
#define D 768
#define BM 128
#define BN 128
#define BKH 64            // halfs per pipeline stage (128 B per row)
#define NSTG (D / BKH)    // 12
#define MARGIN 1.0f
#define SH 72             // halfs per smem row (144 B) - conflict-free pad
#define BUF_HALFS (128 * SH)            // 9216 halfs = 18432 B
#define SMEM_BYTES (4 * BUF_HALFS * 2)  // 73728

#define NTILE 32          // 4096/128
#define NUNITS (NTILE * (NTILE + 1) / 2)  // 528

__device__ __align__(128) __half g_e[N * D];  // normalized fp16 embeddings
__device__ float g_pkey[N];  // min positive dot + 4 (inf if none)
__device__ float g_nkey[N];  // max negative dot + 4 (0 if none)
__device__ unsigned int g_done = 0;

// ---------------- PTX helpers ---------------------------------------------
__device__ __forceinline__ uint32_t smem_u32(const void* p) {
    uint32_t a;
    asm("{ .reg .u64 t; cvta.to.shared.u64 t, %1; cvt.u32.u64 %0, t; }"
        : "=r"(a) : "l"(p));
    return a;
}
#define CP_ASYNC16(dst, src) \
    asm volatile("cp.async.cg.shared.global [%0], [%1], 16;" \
                 :: "r"(dst), "l"(src) : "memory")
#define CP_COMMIT() asm volatile("cp.async.commit_group;" ::: "memory")
#define CP_WAIT(n)  asm volatile("cp.async.wait_group %0;" :: "n"(n) : "memory")

#define LDSM_X4(r0, r1, r2, r3, addr) \
    asm volatile("ldmatrix.sync.aligned.m8n8.x4.shared.b16 {%0,%1,%2,%3}, [%4];" \
                 : "=r"(r0), "=r"(r1), "=r"(r2), "=r"(r3) : "r"(addr))

__device__ __forceinline__ void mma_f16(float* d, const uint32_t* a,
                                        const uint32_t* b) {
    asm volatile(
        "mma.sync.aligned.m16n8k16.row.col.f32.f16.f16.f32 "
        "{%0,%1,%2,%3}, {%4,%5,%6,%7}, {%8,%9}, {%0,%1,%2,%3};"
        : "+f"(d[0]), "+f"(d[1]), "+f"(d[2]), "+f"(d[3])
        : "r"(a[0]), "r"(a[1]), "r"(a[2]), "r"(a[3]), "r"(b[0]), "r"(b[1]));
}

// ---------------------------------------------------------------------------
// Normalize + fp16 convert; also initializes per-row mining keys.
__global__ void normalize_kernel(const float* __restrict__ emb) {
    int row = blockIdx.x;
    if (threadIdx.x == 0) {
        g_pkey[row] = __int_as_float(0x7f800000);  // +inf
        g_nkey[row] = 0.0f;                        // sentinel
    }
    const float* src = emb + (size_t)row * D;
    __half* dst = g_e + (size_t)row * D;

    float v[3];
    float s = 0.0f;
#pragma unroll
    for (int t = 0; t < 3; t++) {
        v[t] = src[threadIdx.x + t * 256];
        s += v[t] * v[t];
    }
#pragma unroll
    for (int o = 16; o > 0; o >>= 1) s += __shfl_xor_sync(0xffffffffu, s, o);
    __shared__ float red[8];
    if ((threadIdx.x & 31) == 0) red[threadIdx.x >> 5] = s;
    __syncthreads();
    if (threadIdx.x < 32) {
        float x = (threadIdx.x < 8) ? red[threadIdx.x] : 0.0f;
#pragma unroll
        for (int o = 4; o > 0; o >>= 1) x += __shfl_xor_sync(0xffffffffu, x, o);
        if (threadIdx.x == 0) red[0] = x;
    }
    __syncthreads();
    float inv = 1.0f / fmaxf(sqrtf(red[0]), 1e-12f);
#pragma unroll
    for (int t = 0; t < 3; t++)
        dst[threadIdx.x + t * 256] = __float2half_rn(v[t] * inv);
}

// ---------------------------------------------------------------------------
// One upper-triangle 128x128 Gram tile per CTA; fp16 m16n8k16 MMA via
// ldmatrix; batch-hard mining in dot domain (rows AND cols as anchors).
// The last CTA to finish computes the final scalar loss.
__global__ void __launch_bounds__(256, 2)
mine_mma(const long long* __restrict__ labels, float* __restrict__ out) {
    extern __shared__ __half smem[];
    const uint32_t sb = smem_u32(smem);
    __shared__ int s_lr[128], s_lc[128];
    __shared__ int s_last;

    // triangle mapping: u -> (I, J) with I <= J
    int u = blockIdx.x;
    int I = 0;
    while (u >= NTILE - I) { u -= NTILE - I; I++; }
    const int J = I + u;
    const int rowBase = I * BM;
    const int colBase = J * BN;

    const int tid = threadIdx.x;
    const int lane = tid & 31;
    const int warp = tid >> 5;
    const int wy = warp >> 2;   // 0..1
    const int wx = warp & 3;    // 0..3
    const int g = lane >> 2;    // 0..7
    const int t = lane & 3;     // 0..3

    if (tid < 128) s_lr[tid] = (int)labels[rowBase + tid];
    else s_lc[tid - 128] = (int)labels[colBase + tid - 128];

    float acc[4][4][4];
#pragma unroll
    for (int mt = 0; mt < 4; mt++)
#pragma unroll
        for (int nt = 0; nt < 4; nt++)
#pragma unroll
            for (int q = 0; q < 4; q++) acc[mt][nt][q] = 0.0f;

    // ---- prefetch stage 0 ----
    {
        const __half* srcA = g_e + (size_t)rowBase * D;
        const __half* srcB = g_e + (size_t)colBase * D;
#pragma unroll
        for (int i = 0; i < 4; i++) {
            int idx = tid + i * 256;
            int row = idx >> 3, q = idx & 7;
            CP_ASYNC16(sb + row * 144 + q * 16, srcA + (size_t)row * D + q * 8);
            CP_ASYNC16(sb + 2 * BUF_HALFS * 2 + row * 144 + q * 16,
                       srcB + (size_t)row * D + q * 8);
        }
        CP_COMMIT();
    }

    // per-lane LDSM address pieces (half offsets within a buffer)
    const int aRowOff = (wy * 64 + (lane & 15)) * SH + (lane >> 4) * 8;
    const int bRowOff = (wx * 32 + (lane >> 4) * 8 + (lane & 7)) * SH +
                        ((lane >> 3) & 1) * 8;

    for (int st = 0; st < NSTG; st++) {
        const int cur = st & 1;
        if (st + 1 < NSTG) {
            const int nxt = (st + 1) & 1;
            const int k0 = (st + 1) * BKH;
            const __half* srcA = g_e + (size_t)rowBase * D + k0;
            const __half* srcB = g_e + (size_t)colBase * D + k0;
#pragma unroll
            for (int i = 0; i < 4; i++) {
                int idx = tid + i * 256;
                int row = idx >> 3, q = idx & 7;
                CP_ASYNC16(sb + nxt * BUF_HALFS * 2 + row * 144 + q * 16,
                           srcA + (size_t)row * D + q * 8);
                CP_ASYNC16(sb + (2 + nxt) * BUF_HALFS * 2 + row * 144 + q * 16,
                           srcB + (size_t)row * D + q * 8);
            }
            CP_COMMIT();
            CP_WAIT(1);
        } else {
            CP_WAIT(0);
        }
        __syncthreads();

        const uint32_t baseA = sb + cur * BUF_HALFS * 2;
        const uint32_t baseB = sb + (2 + cur) * BUF_HALFS * 2;
#pragma unroll
        for (int ks = 0; ks < 4; ks++) {       // 4 x k16 per stage
            uint32_t a[4][4], b[4][2];
#pragma unroll
            for (int mt = 0; mt < 4; mt++)
                LDSM_X4(a[mt][0], a[mt][1], a[mt][2], a[mt][3],
                        baseA + (aRowOff + mt * 16 * SH + ks * 16) * 2);
#pragma unroll
            for (int p = 0; p < 2; p++)
                LDSM_X4(b[2 * p][0], b[2 * p][1], b[2 * p + 1][0],
                        b[2 * p + 1][1],
                        baseB + (bRowOff + p * 16 * SH + ks * 16) * 2);
#pragma unroll
            for (int mt = 0; mt < 4; mt++)
#pragma unroll
                for (int nt = 0; nt < 4; nt++)
                    mma_f16(acc[mt][nt], a[mt], b[nt]);
        }
        __syncthreads();
    }

    // ---- mining: rows and cols are both anchors --------------------------
    const float INF = __int_as_float(0x7f800000);
    float rp[4][2], rn[4][2];     // row-anchor trackers
    float cpm[4][2], cnm[4][2];   // col-anchor trackers
#pragma unroll
    for (int i = 0; i < 4; i++)
#pragma unroll
        for (int h = 0; h < 2; h++) {
            rp[i][h] = INF; rn[i][h] = -INF;
            cpm[i][h] = INF; cnm[i][h] = -INF;
        }

#pragma unroll
    for (int nt = 0; nt < 4; nt++) {
        const int c0 = colBase + wx * 32 + nt * 8 + 2 * t;
        const int lc0 = s_lc[wx * 32 + nt * 8 + 2 * t];
        const int lc1 = s_lc[wx * 32 + nt * 8 + 2 * t + 1];
#pragma unroll
        for (int mt = 0; mt < 4; mt++) {
            const int r0 = rowBase + wy * 64 + mt * 16 + g;
            const int r1 = r0 + 8;
            const int lr0 = s_lr[wy * 64 + mt * 16 + g];
            const int lr1 = s_lr[wy * 64 + mt * 16 + g + 8];
            const float d0 = acc[mt][nt][0], d1 = acc[mt][nt][1];
            const float d2 = acc[mt][nt][2], d3 = acc[mt][nt][3];
            if (lr0 == lc0) {
                if (r0 != c0) { rp[mt][0] = fminf(rp[mt][0], d0);
                                cpm[nt][0] = fminf(cpm[nt][0], d0); }
            } else { rn[mt][0] = fmaxf(rn[mt][0], d0);
                     cnm[nt][0] = fmaxf(cnm[nt][0], d0); }
            if (lr0 == lc1) {
                if (r0 != c0 + 1) { rp[mt][0] = fminf(rp[mt][0], d1);
                                    cpm[nt][1] = fminf(cpm[nt][1], d1); }
            } else { rn[mt][0] = fmaxf(rn[mt][0], d1);
                     cnm[nt][1] = fmaxf(cnm[nt][1], d1); }
            if (lr1 == lc0) {
                if (r1 != c0) { rp[mt][1] = fminf(rp[mt][1], d2);
                                cpm[nt][0] = fminf(cpm[nt][0], d2); }
            } else { rn[mt][1] = fmaxf(rn[mt][1], d2);
                     cnm[nt][0] = fmaxf(cnm[nt][0], d2); }
            if (lr1 == lc1) {
                if (r1 != c0 + 1) { rp[mt][1] = fminf(rp[mt][1], d3);
                                    cpm[nt][1] = fminf(cpm[nt][1], d3); }
            } else { rn[mt][1] = fmaxf(rn[mt][1], d3);
                     cnm[nt][1] = fmaxf(cnm[nt][1], d3); }
        }
    }

    // row-anchor reduce across t lanes
#pragma unroll
    for (int mt = 0; mt < 4; mt++)
#pragma unroll
        for (int h = 0; h < 2; h++) {
            float p = rp[mt][h], n = rn[mt][h];
            p = fminf(p, __shfl_xor_sync(0xffffffffu, p, 1));
            p = fminf(p, __shfl_xor_sync(0xffffffffu, p, 2));
            n = fmaxf(n, __shfl_xor_sync(0xffffffffu, n, 1));
            n = fmaxf(n, __shfl_xor_sync(0xffffffffu, n, 2));
            if (t == 0) {
                int r = rowBase + wy * 64 + mt * 16 + g + h * 8;
                if (p < 1e30f)
                    atomicMin(reinterpret_cast<int*>(&g_pkey[r]),
                              __float_as_int(p + 4.0f));
                if (n > -1e30f)
                    atomicMax(reinterpret_cast<int*>(&g_nkey[r]),
                              __float_as_int(n + 4.0f));
            }
        }

    // col-anchor reduce across g lanes
#pragma unroll
    for (int nt = 0; nt < 4; nt++)
#pragma unroll
        for (int h = 0; h < 2; h++) {
            float p = cpm[nt][h], n = cnm[nt][h];
            p = fminf(p, __shfl_xor_sync(0xffffffffu, p, 4));
            p = fminf(p, __shfl_xor_sync(0xffffffffu, p, 8));
            p = fminf(p, __shfl_xor_sync(0xffffffffu, p, 16));
            n = fmaxf(n, __shfl_xor_sync(0xffffffffu, n, 4));
            n = fmaxf(n, __shfl_xor_sync(0xffffffffu, n, 8));
            n = fmaxf(n, __shfl_xor_sync(0xffffffffu, n, 16));
            if (g == 0) {
                int c = colBase + wx * 32 + nt * 8 + 2 * t + h;
                if (p < 1e30f)
                    atomicMin(reinterpret_cast<int*>(&g_pkey[c]),
                              __float_as_int(p + 4.0f));
                if (n > -1e30f)
                    atomicMax(reinterpret_cast<int*>(&g_nkey[c]),
                              __float_as_int(n + 4.0f));
            }
        }

    // ---- last CTA computes the final loss ---------------------------------
    __threadfence();
    __syncthreads();
    if (tid == 0) {
        unsigned int v = atomicAdd(&g_done, 1u);
        s_last = (v == NUNITS - 1);
    }
    __syncthreads();
    if (!s_last) return;
    __threadfence();

    float sum = 0.0f, cnt = 0.0f;
    for (int i = tid; i < N; i += 256) {
        float pk = g_pkey[i];
        float nk = g_nkey[i];
        if (pk < 1e30f) {
            cnt += 1.0f;
            float dap = sqrtf(fmaxf(2.0f - 2.0f * (pk - 4.0f), 0.0f) + 1e-12f);
            float dan = (nk > 0.0f)
                ? sqrtf(fmaxf(2.0f - 2.0f * (nk - 4.0f), 0.0f) + 1e-12f)
                : 1e30f;
            sum += fmaxf(dap - dan + MARGIN, 0.0f);
        }
    }
#pragma unroll
    for (int o = 16; o > 0; o >>= 1) {
        sum += __shfl_xor_sync(0xffffffffu, sum, o);
        cnt += __shfl_xor_sync(0xffffffffu, cnt, o);
    }
    __shared__ float rs[8], rc[8];
    if ((tid & 31) == 0) { rs[tid >> 5] = sum; rc[tid >> 5] = cnt; }
    __syncthreads();
    if (tid == 0) {
        float S = 0.0f, C = 0.0f;
#pragma unroll
        for (int w = 0; w < 8; w++) { S += rs[w]; C += rc[w]; }
        out[0] = S / fmaxf(C, 1.0f);
        g_done = 0;  // reset for next graph replay
    }
}

// ---------------------------------------------------------------------------
extern "C" void kernel_launch(void* const* d_in, const int* in_sizes, int n_in,
                              void* d_out, int out_size) {
    const float* emb = (const float*)d_in[0];
    const long long* labels = (const long long*)d_in[1];
    float* out = (float*)d_out;

    static int configured = 0;
    if (!configured) {
        cudaFuncSetAttribute(mine_mma, cudaFuncAttributeMaxDynamicSharedMemorySize,
                             SMEM_BYTES);
        configured = 1;
    }

    normalize_kernel<<<N, 256>>>(emb);
    mine_mma<<<NUNITS, 256, SMEM_BYTES>>>(labels, out);
}